// round 1
// baseline (speedup 1.0000x reference)
#include <cuda_runtime.h>

#define C 32
#define BMAX 16
#define EPS 1e-5f

// Scratch (device globals: no allocation allowed in kernel_launch)
__device__ float g_sum[BMAX * C];
__device__ float g_sq[BMAX * C];
__device__ float g_cnt[BMAX];
__device__ float g_scale[BMAX * C];
__device__ float g_shift[BMAX * C];

// ---------------------------------------------------------------------------
// Kernel 0: zero the accumulators (must run every graph replay)
// ---------------------------------------------------------------------------
__global__ void zero_stats_kernel() {
    int i = threadIdx.x;
    if (i < BMAX * C) { g_sum[i] = 0.0f; g_sq[i] = 0.0f; }
    if (i < BMAX) g_cnt[i] = 0.0f;
}

// ---------------------------------------------------------------------------
// Kernel 1: per-segment sum / sumsq / count.
// One warp owns a contiguous chunk of rows; lane j owns channel j.
// batch_id is sorted, so if first==last batch in the chunk we take a tight
// loop with no per-row batch_id loads and a single flush.
// ---------------------------------------------------------------------------
__global__ void reduce_kernel(const float* __restrict__ data,
                              const int* __restrict__ bid,
                              int N, int rows_per_warp) {
    int warp = (int)((blockIdx.x * blockDim.x + threadIdx.x) >> 5);
    int lane = threadIdx.x & 31;

    int r0 = warp * rows_per_warp;
    if (r0 >= N) return;
    int r1 = r0 + rows_per_warp;
    if (r1 > N) r1 = N;

    int b_first = bid[r0];
    int b_last = bid[r1 - 1];

    float s = 0.0f, q = 0.0f;

    if (b_first == b_last) {
        // Fast path: single segment — pure streaming.
        const float* p = data + (size_t)r0 * C + lane;
        int rows = r1 - r0;
        int r = 0;
        #pragma unroll 4
        for (; r + 4 <= rows; r += 4) {
            float x0 = p[(size_t)(r + 0) * C];
            float x1 = p[(size_t)(r + 1) * C];
            float x2 = p[(size_t)(r + 2) * C];
            float x3 = p[(size_t)(r + 3) * C];
            s += x0 + x1 + x2 + x3;
            q += x0 * x0 + x1 * x1 + x2 * x2 + x3 * x3;
        }
        for (; r < rows; ++r) {
            float x = p[(size_t)r * C];
            s += x; q += x * x;
        }
        atomicAdd(&g_sum[b_first * C + lane], s);
        atomicAdd(&g_sq[b_first * C + lane], q);
        if (lane == 0) atomicAdd(&g_cnt[b_first], (float)rows);
    } else {
        // Slow path: chunk crosses a segment boundary (<= 15 warps total).
        int cur = b_first;
        float cnt = 0.0f;
        for (int r = r0; r < r1; ++r) {
            int b = bid[r];
            if (b != cur) {
                atomicAdd(&g_sum[cur * C + lane], s);
                atomicAdd(&g_sq[cur * C + lane], q);
                if (lane == 0) atomicAdd(&g_cnt[cur], cnt);
                s = 0.0f; q = 0.0f; cnt = 0.0f; cur = b;
            }
            float x = data[(size_t)r * C + lane];
            s += x; q += x * x; cnt += 1.0f;
        }
        atomicAdd(&g_sum[cur * C + lane], s);
        atomicAdd(&g_sq[cur * C + lane], q);
        if (lane == 0) atomicAdd(&g_cnt[cur], cnt);
    }
}

// ---------------------------------------------------------------------------
// Kernel 2: fold stats into per-(b,c) scale/shift.
// out = (x - mean) * inv_std * w + bias  ==  x*scale + shift
// ---------------------------------------------------------------------------
__global__ void finalize_kernel(const float* __restrict__ w,
                                const float* __restrict__ bias) {
    int i = threadIdx.x;           // 0..BMAX*C-1
    if (i >= BMAX * C) return;
    int b = i / C, c = i % C;
    float cnt = g_cnt[b];
    float norm = 1.0f / (cnt + EPS);
    float sum = g_sum[i];
    float mean = sum * norm;
    float var = (g_sq[i] - 2.0f * mean * sum + mean * mean * cnt) * norm;
    float inv_std = rsqrtf(var + EPS);
    float wc = w ? w[c] : 1.0f;
    float bc = bias ? bias[c] : 0.0f;
    float sc = inv_std * wc;
    g_scale[i] = sc;
    g_shift[i] = bc - mean * sc;
}

// ---------------------------------------------------------------------------
// Kernel 3: normalize.  float4 streaming; 8 float4 per row.
// ---------------------------------------------------------------------------
__global__ void normalize_kernel(const float4* __restrict__ data4,
                                 const int* __restrict__ bid,
                                 float4* __restrict__ out4, int n4) {
    __shared__ float4 s_scale[BMAX * C / 4];
    __shared__ float4 s_shift[BMAX * C / 4];
    for (int i = threadIdx.x; i < BMAX * C / 4; i += blockDim.x) {
        s_scale[i] = reinterpret_cast<const float4*>(g_scale)[i];
        s_shift[i] = reinterpret_cast<const float4*>(g_shift)[i];
    }
    __syncthreads();

    int i = blockIdx.x * blockDim.x + threadIdx.x;
    if (i >= n4) return;
    int row = i >> 3;              // 8 float4 per 32-channel row
    int b = bid[row];
    int q = (b << 3) | (i & 7);    // index into [B][8] float4 table
    float4 d = data4[i];
    float4 sc = s_scale[q];
    float4 sh = s_shift[q];
    float4 o;
    o.x = fmaf(d.x, sc.x, sh.x);
    o.y = fmaf(d.y, sc.y, sh.y);
    o.z = fmaf(d.z, sc.z, sh.z);
    o.w = fmaf(d.w, sc.w, sh.w);
    out4[i] = o;
}

// ---------------------------------------------------------------------------
extern "C" void kernel_launch(void* const* d_in, const int* in_sizes, int n_in,
                              void* d_out, int out_size) {
    const float* data = (const float*)d_in[0];
    const int* bid = (const int*)d_in[1];
    int N = in_sizes[0] / C;

    // Locate weights/bias among the remaining inputs (size-32 fp32 arrays,
    // in order); a size-1 input is batch_size (fixed at 16, unused on host).
    const float* w = nullptr;
    const float* bias = nullptr;
    for (int i = 2; i < n_in; ++i) {
        if (in_sizes[i] == C) {
            if (!w) w = (const float*)d_in[i];
            else if (!bias) bias = (const float*)d_in[i];
        }
    }

    zero_stats_kernel<<<1, BMAX * C>>>();

    const int threads = 256;
    const int blocks = 148 * 8;                 // 9472 warps
    int warps = blocks * (threads / 32);
    int rpw = (N + warps - 1) / warps;
    reduce_kernel<<<blocks, threads>>>(data, bid, N, rpw);

    finalize_kernel<<<1, BMAX * C>>>(w, bias);

    int n4 = N * (C / 4);
    int nblocks = (n4 + threads - 1) / threads;
    normalize_kernel<<<nblocks, threads>>>((const float4*)data, bid,
                                           (float4*)d_out, n4);
}

// round 2
// speedup vs baseline: 1.0021x; 1.0021x over previous
#include <cuda_runtime.h>

#define C 32
#define BMAX 16
#define EPS 1e-5f

// Scratch (device globals: no allocation allowed in kernel_launch)
__device__ float g_sum[BMAX * C];
__device__ float g_sq[BMAX * C];
__device__ float g_cnt[BMAX];
__device__ float g_scale[BMAX * C];
__device__ float g_shift[BMAX * C];

// ---------------------------------------------------------------------------
// Kernel 0: zero the accumulators (must run every graph replay)
// ---------------------------------------------------------------------------
__global__ void zero_stats_kernel() {
    int i = threadIdx.x;
    if (i < BMAX * C) { g_sum[i] = 0.0f; g_sq[i] = 0.0f; }
    if (i < BMAX) g_cnt[i] = 0.0f;
}

// ---------------------------------------------------------------------------
// Kernel 1: per-segment sum / sumsq / count.
// One warp owns a contiguous chunk of rows; lane j owns channel j.
// batch_id is sorted, so if first==last batch in the chunk we take a tight
// loop with no per-row batch_id loads and a single flush.
// ---------------------------------------------------------------------------
__global__ void reduce_kernel(const float* __restrict__ data,
                              const int* __restrict__ bid,
                              int N, int rows_per_warp) {
    int warp = (int)((blockIdx.x * blockDim.x + threadIdx.x) >> 5);
    int lane = threadIdx.x & 31;

    int r0 = warp * rows_per_warp;
    if (r0 >= N) return;
    int r1 = r0 + rows_per_warp;
    if (r1 > N) r1 = N;

    int b_first = bid[r0];
    int b_last = bid[r1 - 1];

    float s = 0.0f, q = 0.0f;

    if (b_first == b_last) {
        // Fast path: single segment — pure streaming.
        const float* p = data + (size_t)r0 * C + lane;
        int rows = r1 - r0;
        int r = 0;
        #pragma unroll 4
        for (; r + 4 <= rows; r += 4) {
            float x0 = p[(size_t)(r + 0) * C];
            float x1 = p[(size_t)(r + 1) * C];
            float x2 = p[(size_t)(r + 2) * C];
            float x3 = p[(size_t)(r + 3) * C];
            s += x0 + x1 + x2 + x3;
            q += x0 * x0 + x1 * x1 + x2 * x2 + x3 * x3;
        }
        for (; r < rows; ++r) {
            float x = p[(size_t)r * C];
            s += x; q += x * x;
        }
        atomicAdd(&g_sum[b_first * C + lane], s);
        atomicAdd(&g_sq[b_first * C + lane], q);
        if (lane == 0) atomicAdd(&g_cnt[b_first], (float)rows);
    } else {
        // Slow path: chunk crosses a segment boundary (<= 15 warps total).
        int cur = b_first;
        float cnt = 0.0f;
        for (int r = r0; r < r1; ++r) {
            int b = bid[r];
            if (b != cur) {
                atomicAdd(&g_sum[cur * C + lane], s);
                atomicAdd(&g_sq[cur * C + lane], q);
                if (lane == 0) atomicAdd(&g_cnt[cur], cnt);
                s = 0.0f; q = 0.0f; cnt = 0.0f; cur = b;
            }
            float x = data[(size_t)r * C + lane];
            s += x; q += x * x; cnt += 1.0f;
        }
        atomicAdd(&g_sum[cur * C + lane], s);
        atomicAdd(&g_sq[cur * C + lane], q);
        if (lane == 0) atomicAdd(&g_cnt[cur], cnt);
    }
}

// ---------------------------------------------------------------------------
// Kernel 2: fold stats into per-(b,c) scale/shift.
// out = (x - mean) * inv_std * w + bias  ==  x*scale + shift
// ---------------------------------------------------------------------------
__global__ void finalize_kernel(const float* __restrict__ w,
                                const float* __restrict__ bias) {
    int i = threadIdx.x;           // 0..BMAX*C-1
    if (i >= BMAX * C) return;
    int b = i / C, c = i % C;
    float cnt = g_cnt[b];
    float norm = 1.0f / (cnt + EPS);
    float sum = g_sum[i];
    float mean = sum * norm;
    float var = (g_sq[i] - 2.0f * mean * sum + mean * mean * cnt) * norm;
    float inv_std = rsqrtf(var + EPS);
    float wc = w ? w[c] : 1.0f;
    float bc = bias ? bias[c] : 0.0f;
    float sc = inv_std * wc;
    g_scale[i] = sc;
    g_shift[i] = bc - mean * sc;
}

// ---------------------------------------------------------------------------
// Kernel 3: normalize.  float4 streaming; 8 float4 per row.
// ---------------------------------------------------------------------------
__global__ void normalize_kernel(const float4* __restrict__ data4,
                                 const int* __restrict__ bid,
                                 float4* __restrict__ out4, int n4) {
    __shared__ float4 s_scale[BMAX * C / 4];
    __shared__ float4 s_shift[BMAX * C / 4];
    for (int i = threadIdx.x; i < BMAX * C / 4; i += blockDim.x) {
        s_scale[i] = reinterpret_cast<const float4*>(g_scale)[i];
        s_shift[i] = reinterpret_cast<const float4*>(g_shift)[i];
    }
    __syncthreads();

    int i = blockIdx.x * blockDim.x + threadIdx.x;
    if (i >= n4) return;
    int row = i >> 3;              // 8 float4 per 32-channel row
    int b = bid[row];
    int q = (b << 3) | (i & 7);    // index into [B][8] float4 table
    float4 d = data4[i];
    float4 sc = s_scale[q];
    float4 sh = s_shift[q];
    float4 o;
    o.x = fmaf(d.x, sc.x, sh.x);
    o.y = fmaf(d.y, sc.y, sh.y);
    o.z = fmaf(d.z, sc.z, sh.z);
    o.w = fmaf(d.w, sc.w, sh.w);
    out4[i] = o;
}

// ---------------------------------------------------------------------------
extern "C" void kernel_launch(void* const* d_in, const int* in_sizes, int n_in,
                              void* d_out, int out_size) {
    const float* data = (const float*)d_in[0];
    const int* bid = (const int*)d_in[1];
    int N = in_sizes[0] / C;

    // Locate weights/bias among the remaining inputs (size-32 fp32 arrays,
    // in order); a size-1 input is batch_size (fixed at 16, unused on host).
    const float* w = nullptr;
    const float* bias = nullptr;
    for (int i = 2; i < n_in; ++i) {
        if (in_sizes[i] == C) {
            if (!w) w = (const float*)d_in[i];
            else if (!bias) bias = (const float*)d_in[i];
        }
    }

    zero_stats_kernel<<<1, BMAX * C>>>();

    const int threads = 256;
    const int blocks = 148 * 8;                 // 9472 warps
    int warps = blocks * (threads / 32);
    int rpw = (N + warps - 1) / warps;
    reduce_kernel<<<blocks, threads>>>(data, bid, N, rpw);

    finalize_kernel<<<1, BMAX * C>>>(w, bias);

    int n4 = N * (C / 4);
    int nblocks = (n4 + threads - 1) / threads;
    normalize_kernel<<<nblocks, threads>>>((const float4*)data, bid,
                                           (float4*)d_out, n4);
}